// round 1
// baseline (speedup 1.0000x reference)
#include <cuda_runtime.h>

#define D_MODEL 1024
#define N_HEADS 16
#define D_HEAD  64
#define B_SIZE  2
#define T_SEQ   2048
#define M_ROWS  (B_SIZE * T_SEQ)   // 4096

// Scratch (allocation-free rule: __device__ globals)
__device__ float g_Q[M_ROWS * D_MODEL];     // [B,H,T,64] head layout
__device__ float g_K[M_ROWS * D_MODEL];
__device__ float g_V[M_ROWS * D_MODEL];
__device__ float g_attn[M_ROWS * D_MODEL];  // [B,T,1024] row-major

// ---------------------------------------------------------------------------
// Tiled SGEMM: C = A(MxK) @ W(KxN) + bias
// BM=128, BN=128, BK=16, TM=TN=8, 256 threads.
// HEAD_LAYOUT=1: scatter C[row, col] -> [b, h, t, d] with row=b*T+t, col=h*64+d
// ---------------------------------------------------------------------------
template <int HEAD_LAYOUT>
__global__ __launch_bounds__(256, 2)
void gemm_bias_kernel(const float* __restrict__ A,
                      const float* __restrict__ W,
                      const float* __restrict__ bias,
                      float* __restrict__ C,
                      int M, int N, int K)
{
    constexpr int BM = 128, BN = 128, BK = 16;
    __shared__ float As[BK][BM];   // transposed: As[k][m]
    __shared__ float Bs[BK][BN];   // natural:    Bs[k][n]

    const int tid  = threadIdx.x;          // 0..255
    const int tx   = tid & 15;             // 0..15 -> 8 cols each
    const int ty   = tid >> 4;             // 0..15 -> 8 rows each
    const int brow = blockIdx.y * BM;
    const int bcol = blockIdx.x * BN;

    // A-tile load mapping: 128x16 floats = 2 float4 per thread
    const int a_r = tid >> 2;              // 0..63 (rows a_r, a_r+64)
    const int a_c = (tid & 3) * 4;         // k offset 0,4,8,12
    // B-tile load mapping: 16x128 floats = 2 float4 per thread
    const int b_r = tid >> 5;              // 0..7 (rows b_r, b_r+8)
    const int b_c = (tid & 31) * 4;        // col offset

    float acc[8][8];
    #pragma unroll
    for (int m = 0; m < 8; m++)
        #pragma unroll
        for (int n = 0; n < 8; n++) acc[m][n] = 0.0f;

    for (int k0 = 0; k0 < K; k0 += BK) {
        #pragma unroll
        for (int rr = 0; rr < 2; rr++) {
            const int r = a_r + rr * 64;
            float4 v = *reinterpret_cast<const float4*>(
                &A[(size_t)(brow + r) * K + k0 + a_c]);
            As[a_c + 0][r] = v.x;
            As[a_c + 1][r] = v.y;
            As[a_c + 2][r] = v.z;
            As[a_c + 3][r] = v.w;
        }
        #pragma unroll
        for (int rr = 0; rr < 2; rr++) {
            const int r = b_r + rr * 8;
            float4 v = *reinterpret_cast<const float4*>(
                &W[(size_t)(k0 + r) * N + bcol + b_c]);
            *reinterpret_cast<float4*>(&Bs[r][b_c]) = v;
        }
        __syncthreads();

        #pragma unroll
        for (int k = 0; k < BK; k++) {
            float4 a0 = *reinterpret_cast<const float4*>(&As[k][ty * 8]);
            float4 a1 = *reinterpret_cast<const float4*>(&As[k][ty * 8 + 4]);
            float4 b0 = *reinterpret_cast<const float4*>(&Bs[k][tx * 8]);
            float4 b1 = *reinterpret_cast<const float4*>(&Bs[k][tx * 8 + 4]);
            float ra[8] = {a0.x, a0.y, a0.z, a0.w, a1.x, a1.y, a1.z, a1.w};
            float rb[8] = {b0.x, b0.y, b0.z, b0.w, b1.x, b1.y, b1.z, b1.w};
            #pragma unroll
            for (int m = 0; m < 8; m++)
                #pragma unroll
                for (int n = 0; n < 8; n++)
                    acc[m][n] = fmaf(ra[m], rb[n], acc[m][n]);
        }
        __syncthreads();
    }

    #pragma unroll
    for (int m = 0; m < 8; m++) {
        const int row = brow + ty * 8 + m;
        #pragma unroll
        for (int n = 0; n < 8; n++) {
            const int col = bcol + tx * 8 + n;
            const float v = acc[m][n] + bias[col];
            if (HEAD_LAYOUT) {
                const int b = row / T_SEQ, t = row % T_SEQ;
                const int h = col / D_HEAD, d = col % D_HEAD;
                C[(((size_t)(b * N_HEADS + h) * T_SEQ) + t) * D_HEAD + d] = v;
            } else {
                C[(size_t)row * N + col] = v;
            }
        }
    }
}

// ---------------------------------------------------------------------------
// Flash-attention (causal). Block = 64 queries, steps of 32 keys.
// Q/K stored d-major in shared for the S-GEMM; S staged in padded shared.
// 256 threads: S microtile 4x2, O microtile 4x4.
// ---------------------------------------------------------------------------
__global__ __launch_bounds__(256)
void attn_kernel(const float* __restrict__ Qh,
                 const float* __restrict__ Kh,
                 const float* __restrict__ Vh,
                 float* __restrict__ out)
{
    constexpr int BQ = 64, BKV = 32;
    __shared__ float Qs[D_HEAD][BQ];        // [d][i], pre-scaled
    __shared__ float Ks[D_HEAD][BKV + 1];   // [d][j]
    __shared__ float Vs[BKV][D_HEAD];       // [j][d]
    __shared__ float Ss[BQ][BKV + 1];       // [i][j]
    __shared__ float row_m[BQ], row_l[BQ], row_scale[BQ];

    const int tid = threadIdx.x;            // 0..255
    const int tx  = tid & 15;
    const int ty  = tid >> 4;
    const int bh  = blockIdx.y;              // 0..31
    const int b   = bh / N_HEADS;
    const int h   = bh % N_HEADS;
    const int q0  = blockIdx.x * BQ;

    const float* Qb = Qh + (size_t)bh * T_SEQ * D_HEAD;
    const float* Kb = Kh + (size_t)bh * T_SEQ * D_HEAD;
    const float* Vb = Vh + (size_t)bh * T_SEQ * D_HEAD;

    // Load Q tile (pre-scaled by 1/sqrt(64) = 0.125)
    for (int idx = tid; idx < BQ * D_HEAD; idx += 256) {
        const int i = idx >> 6;     // / 64
        const int d = idx & 63;
        Qs[d][i] = Qb[(size_t)(q0 + i) * D_HEAD + d] * 0.125f;
    }
    if (tid < BQ) { row_m[tid] = -1e30f; row_l[tid] = 0.0f; }

    float o[4][4];
    #pragma unroll
    for (int m = 0; m < 4; m++)
        #pragma unroll
        for (int n = 0; n < 4; n++) o[m][n] = 0.0f;

    __syncthreads();

    const int nkt = 2 * blockIdx.x + 2;      // key tiles covering [0, q0+64)
    for (int kt = 0; kt < nkt; kt++) {
        const int k0 = kt * BKV;

        for (int idx = tid; idx < BKV * D_HEAD; idx += 256) {
            const int j = idx >> 6;
            const int d = idx & 63;
            Ks[d][j] = Kb[(size_t)(k0 + j) * D_HEAD + d];
            Vs[j][d] = Vb[(size_t)(k0 + j) * D_HEAD + d];
        }
        __syncthreads();

        // S = Q K^T
        float s[4][2] = {{0.f, 0.f}, {0.f, 0.f}, {0.f, 0.f}, {0.f, 0.f}};
        #pragma unroll 8
        for (int d = 0; d < D_HEAD; d++) {
            float ra[4], rb[2];
            #pragma unroll
            for (int m = 0; m < 4; m++) ra[m] = Qs[d][ty * 4 + m];
            #pragma unroll
            for (int n = 0; n < 2; n++) rb[n] = Ks[d][tx * 2 + n];
            #pragma unroll
            for (int m = 0; m < 4; m++)
                #pragma unroll
                for (int n = 0; n < 2; n++)
                    s[m][n] = fmaf(ra[m], rb[n], s[m][n]);
        }

        // Causal mask + stage into shared
        #pragma unroll
        for (int m = 0; m < 4; m++) {
            const int i = ty * 4 + m;
            #pragma unroll
            for (int n = 0; n < 2; n++) {
                const int j = tx * 2 + n;
                float v = s[m][n];
                if (k0 + j > q0 + i) v = -1e30f;
                Ss[i][j] = v;
            }
        }
        __syncthreads();

        // Online softmax per row (threads 0..63, stride-33 rows -> no conflicts)
        if (tid < BQ) {
            const int i = tid;
            const float mo = row_m[i];
            float mx = mo;
            #pragma unroll 8
            for (int j = 0; j < BKV; j++) mx = fmaxf(mx, Ss[i][j]);
            const float sc = __expf(mo - mx);
            float l = row_l[i] * sc;
            #pragma unroll 8
            for (int j = 0; j < BKV; j++) {
                const float p = __expf(Ss[i][j] - mx);
                Ss[i][j] = p;
                l += p;
            }
            row_m[i] = mx;
            row_l[i] = l;
            row_scale[i] = sc;
        }
        __syncthreads();

        // Rescale O and accumulate P @ V
        float scl[4];
        #pragma unroll
        for (int m = 0; m < 4; m++) scl[m] = row_scale[ty * 4 + m];
        #pragma unroll
        for (int m = 0; m < 4; m++)
            #pragma unroll
            for (int n = 0; n < 4; n++) o[m][n] *= scl[m];

        #pragma unroll 4
        for (int j = 0; j < BKV; j++) {
            float rp[4], rv[4];
            #pragma unroll
            for (int m = 0; m < 4; m++) rp[m] = Ss[ty * 4 + m][j];
            #pragma unroll
            for (int n = 0; n < 4; n++) rv[n] = Vs[j][tx * 4 + n];
            #pragma unroll
            for (int m = 0; m < 4; m++)
                #pragma unroll
                for (int n = 0; n < 4; n++)
                    o[m][n] = fmaf(rp[m], rv[n], o[m][n]);
        }
        __syncthreads();
    }

    // Normalize and write to [B, T, D_MODEL]
    #pragma unroll
    for (int m = 0; m < 4; m++) {
        const int i = ty * 4 + m;
        const float inv_l = 1.0f / row_l[i];
        const int t = q0 + i;
        #pragma unroll
        for (int n = 0; n < 4; n++) {
            const int d = tx * 4 + n;
            out[((size_t)(b * T_SEQ + t)) * D_MODEL + h * D_HEAD + d] =
                o[m][n] * inv_l;
        }
    }
}

// ---------------------------------------------------------------------------
extern "C" void kernel_launch(void* const* d_in, const int* in_sizes, int n_in,
                              void* d_out, int out_size)
{
    const float* x  = (const float*)d_in[0];
    const float* Wq = (const float*)d_in[1];
    const float* bq = (const float*)d_in[2];
    const float* Wk = (const float*)d_in[3];
    const float* bk = (const float*)d_in[4];
    const float* Wv = (const float*)d_in[5];
    const float* bv = (const float*)d_in[6];
    const float* Wo = (const float*)d_in[7];
    const float* bo = (const float*)d_in[8];
    float* out = (float*)d_out;

    float *Q, *K, *V, *attn;
    cudaGetSymbolAddress((void**)&Q, g_Q);
    cudaGetSymbolAddress((void**)&K, g_K);
    cudaGetSymbolAddress((void**)&V, g_V);
    cudaGetSymbolAddress((void**)&attn, g_attn);

    const dim3 ggrid(D_MODEL / 128, M_ROWS / 128);  // (8, 32)
    gemm_bias_kernel<1><<<ggrid, 256>>>(x, Wq, bq, Q, M_ROWS, D_MODEL, D_MODEL);
    gemm_bias_kernel<1><<<ggrid, 256>>>(x, Wk, bk, K, M_ROWS, D_MODEL, D_MODEL);
    gemm_bias_kernel<1><<<ggrid, 256>>>(x, Wv, bv, V, M_ROWS, D_MODEL, D_MODEL);

    attn_kernel<<<dim3(T_SEQ / 64, B_SIZE * N_HEADS), 256>>>(Q, K, V, attn);

    gemm_bias_kernel<0><<<ggrid, 256>>>(attn, Wo, bo, out, M_ROWS, D_MODEL, D_MODEL);
}

// round 2
// speedup vs baseline: 1.0367x; 1.0367x over previous
#include <cuda_runtime.h>

#define D_MODEL 1024
#define N_HEADS 16
#define D_HEAD  64
#define B_SIZE  2
#define T_SEQ   2048
#define M_ROWS  (B_SIZE * T_SEQ)   // 4096

// Scratch (allocation-free rule: __device__ globals)
__device__ float g_Q[M_ROWS * D_MODEL];     // [B,H,T,64] head layout
__device__ float g_K[M_ROWS * D_MODEL];
__device__ float g_V[M_ROWS * D_MODEL];
__device__ float g_attn[M_ROWS * D_MODEL];  // [B,T,1024] row-major

// ---------------------------------------------------------------------------
// Tiled SGEMM with double buffering: C = A(MxK) @ W(KxN) + bias
// BM=128, BN=128, BK=16, TM=TN=8, 256 threads.
// ---------------------------------------------------------------------------
template <int HEAD_LAYOUT>
__global__ __launch_bounds__(256, 2)
void gemm_bias_kernel(const float* __restrict__ A,
                      const float* __restrict__ W,
                      const float* __restrict__ bias,
                      float* __restrict__ C,
                      int M, int N, int K)
{
    constexpr int BM = 128, BN = 128, BK = 16;
    __shared__ float As[2][BK][BM];   // transposed: As[buf][k][m]
    __shared__ float Bs[2][BK][BN];   // natural:    Bs[buf][k][n]

    const int tid  = threadIdx.x;          // 0..255
    const int tx   = tid & 15;
    const int ty   = tid >> 4;
    const int brow = blockIdx.y * BM;
    const int bcol = blockIdx.x * BN;

    const int a_r = tid >> 2;               // 0..63 (rows a_r, a_r+64)
    const int a_c = (tid & 3) * 4;          // k offset 0,4,8,12
    const int b_r = tid >> 5;               // 0..7 (rows b_r, b_r+8)
    const int b_c = (tid & 31) * 4;

    float acc[8][8];
    #pragma unroll
    for (int m = 0; m < 8; m++)
        #pragma unroll
        for (int n = 0; n < 8; n++) acc[m][n] = 0.0f;

    float4 av[2], bv[2];
    auto ldg_tile = [&](int k0) {
        #pragma unroll
        for (int rr = 0; rr < 2; rr++)
            av[rr] = *reinterpret_cast<const float4*>(
                &A[(size_t)(brow + a_r + rr * 64) * K + k0 + a_c]);
        #pragma unroll
        for (int rr = 0; rr < 2; rr++)
            bv[rr] = *reinterpret_cast<const float4*>(
                &W[(size_t)(k0 + b_r + rr * 8) * N + bcol + b_c]);
    };
    auto sts_tile = [&](int buf) {
        #pragma unroll
        for (int rr = 0; rr < 2; rr++) {
            const int r = a_r + rr * 64;
            As[buf][a_c + 0][r] = av[rr].x;
            As[buf][a_c + 1][r] = av[rr].y;
            As[buf][a_c + 2][r] = av[rr].z;
            As[buf][a_c + 3][r] = av[rr].w;
        }
        #pragma unroll
        for (int rr = 0; rr < 2; rr++)
            *reinterpret_cast<float4*>(&Bs[buf][b_r + rr * 8][b_c]) = bv[rr];
    };

    const int nk = K / BK;
    ldg_tile(0);
    sts_tile(0);
    __syncthreads();

    for (int t = 0; t < nk; t++) {
        if (t + 1 < nk) ldg_tile((t + 1) * BK);
        const int cur = t & 1;
        #pragma unroll
        for (int k = 0; k < BK; k++) {
            float4 a0 = *reinterpret_cast<const float4*>(&As[cur][k][ty * 8]);
            float4 a1 = *reinterpret_cast<const float4*>(&As[cur][k][ty * 8 + 4]);
            float4 b0 = *reinterpret_cast<const float4*>(&Bs[cur][k][tx * 8]);
            float4 b1 = *reinterpret_cast<const float4*>(&Bs[cur][k][tx * 8 + 4]);
            float ra[8] = {a0.x, a0.y, a0.z, a0.w, a1.x, a1.y, a1.z, a1.w};
            float rb[8] = {b0.x, b0.y, b0.z, b0.w, b1.x, b1.y, b1.z, b1.w};
            #pragma unroll
            for (int m = 0; m < 8; m++)
                #pragma unroll
                for (int n = 0; n < 8; n++)
                    acc[m][n] = fmaf(ra[m], rb[n], acc[m][n]);
        }
        if (t + 1 < nk) {
            sts_tile(1 - cur);
            __syncthreads();
        }
    }

    #pragma unroll
    for (int m = 0; m < 8; m++) {
        const int row = brow + ty * 8 + m;
        #pragma unroll
        for (int n = 0; n < 8; n++) {
            const int col = bcol + tx * 8 + n;
            const float v = acc[m][n] + bias[col];
            if (HEAD_LAYOUT) {
                const int b = row >> 11, t_ = row & (T_SEQ - 1);
                const int h = col >> 6,  d  = col & 63;
                C[(((size_t)(b * N_HEADS + h) * T_SEQ) + t_) * D_HEAD + d] = v;
            } else {
                C[(size_t)row * N + col] = v;
            }
        }
    }
}

// ---------------------------------------------------------------------------
// Flash-attention v2 (causal). BQ = BKV = 128, 512 threads.
// S microtile 8x4 (float4 LDS), PV microtile 4x4 with j-unroll-4 float4 reads.
// Softmax distributed over all 512 threads. K/V register-prefetched.
// Dynamic smem: Qs[64][128] + Ks[64][128] + Vs[128][64] + Ss[128][132] + rows.
// ---------------------------------------------------------------------------
#define SS_STRIDE 132
#define ATTN_SMEM_FLOATS (8192 + 8192 + 8192 + 128 * SS_STRIDE + 3 * 128)
#define ATTN_SMEM_BYTES  (ATTN_SMEM_FLOATS * 4)

__global__ __launch_bounds__(512, 1)
void attn_kernel(const float* __restrict__ Qh,
                 const float* __restrict__ Kh,
                 const float* __restrict__ Vh,
                 float* __restrict__ out)
{
    extern __shared__ float sm[];
    float* Qs    = sm;                    // [d][i]  64x128, pre-scaled
    float* Ks    = sm + 8192;             // [d][j]  64x128
    float* Vs    = sm + 16384;            // [j][d]  128x64
    float* Ss    = sm + 24576;            // [i][j]  128x132 (padded)
    float* row_m = sm + 24576 + 128 * SS_STRIDE;
    float* row_l = row_m + 128;
    float* row_s = row_l + 128;

    const int tid = threadIdx.x;
    const int bx  = gridDim.x - 1 - blockIdx.x;   // heavy blocks first
    const int bh  = blockIdx.y;
    const int b   = bh >> 4;
    const int h   = bh & 15;
    const int q0  = bx * 128;

    const float* Qb = Qh + (size_t)bh * T_SEQ * D_HEAD;
    const float* Kb = Kh + (size_t)bh * T_SEQ * D_HEAD;
    const float* Vb = Vh + (size_t)bh * T_SEQ * D_HEAD;

    // ---- Load Q tile transposed + pre-scaled (conflict-free STS) ----
    {
        const int i   = tid & 127;
        const int dq0 = tid >> 7;     // 0..3
        #pragma unroll
        for (int it = 0; it < 4; it++) {
            const int dq = dq0 + it * 4;
            float4 v = *reinterpret_cast<const float4*>(
                &Qb[(size_t)(q0 + i) * D_HEAD + dq * 4]);
            Qs[(dq * 4 + 0) * 128 + i] = v.x * 0.125f;
            Qs[(dq * 4 + 1) * 128 + i] = v.y * 0.125f;
            Qs[(dq * 4 + 2) * 128 + i] = v.z * 0.125f;
            Qs[(dq * 4 + 3) * 128 + i] = v.w * 0.125f;
        }
    }
    if (tid < 128) { row_m[tid] = -1e30f; row_l[tid] = 0.0f; }

    // thread-tile ids
    const int ty  = tid >> 5;   // S-GEMM: i = ty*8   (0..15)
    const int tx  = tid & 31;   // S-GEMM: j = tx*4
    const int ty2 = tid >> 4;   // PV: i = ty2*4      (0..31)
    const int tx2 = tid & 15;   // PV: d = tx2*4

    float o[4][4];
    #pragma unroll
    for (int m = 0; m < 4; m++)
        #pragma unroll
        for (int n = 0; n < 4; n++) o[m][n] = 0.0f;

    // K/V load mappings + register prefetch buffers
    const int kj  = tid & 127;
    const int kq0 = tid >> 7;
    float4 kreg[4], vreg[4];

    auto ldg_k = [&](int k0) {
        #pragma unroll
        for (int it = 0; it < 4; it++) {
            const int dq = kq0 + it * 4;
            kreg[it] = *reinterpret_cast<const float4*>(
                &Kb[(size_t)(k0 + kj) * D_HEAD + dq * 4]);
        }
    };
    auto sts_k = [&]() {
        #pragma unroll
        for (int it = 0; it < 4; it++) {
            const int dq = kq0 + it * 4;
            Ks[(dq * 4 + 0) * 128 + kj] = kreg[it].x;
            Ks[(dq * 4 + 1) * 128 + kj] = kreg[it].y;
            Ks[(dq * 4 + 2) * 128 + kj] = kreg[it].z;
            Ks[(dq * 4 + 3) * 128 + kj] = kreg[it].w;
        }
    };
    auto ldg_v = [&](int k0) {
        #pragma unroll
        for (int it = 0; it < 4; it++) {
            const int idx = tid + it * 512;
            const int j = idx >> 4, dq = idx & 15;
            vreg[it] = *reinterpret_cast<const float4*>(
                &Vb[(size_t)(k0 + j) * D_HEAD + dq * 4]);
        }
    };
    auto sts_v = [&]() {
        #pragma unroll
        for (int it = 0; it < 4; it++) {
            const int idx = tid + it * 512;
            const int j = idx >> 4, dq = idx & 15;
            *reinterpret_cast<float4*>(&Vs[j * D_HEAD + dq * 4]) = vreg[it];
        }
    };

    // preload tile 0
    ldg_k(0); ldg_v(0);
    sts_k(); sts_v();
    __syncthreads();

    const int nkt = bx + 1;
    for (int kt = 0; kt < nkt; kt++) {
        const int k0 = kt * 128;
        const bool have_next = (kt + 1 < nkt);
        if (have_next) { ldg_k(k0 + 128); ldg_v(k0 + 128); }

        // ---- S = Q K^T (8x4 microtile, float4 LDS) ----
        float s[8][4];
        #pragma unroll
        for (int m = 0; m < 8; m++)
            #pragma unroll
            for (int n = 0; n < 4; n++) s[m][n] = 0.0f;

        #pragma unroll 16
        for (int d = 0; d < D_HEAD; d++) {
            float4 a0 = *reinterpret_cast<const float4*>(&Qs[d * 128 + ty * 8]);
            float4 a1 = *reinterpret_cast<const float4*>(&Qs[d * 128 + ty * 8 + 4]);
            float4 bb = *reinterpret_cast<const float4*>(&Ks[d * 128 + tx * 4]);
            float ra[8] = {a0.x, a0.y, a0.z, a0.w, a1.x, a1.y, a1.z, a1.w};
            float rb[4] = {bb.x, bb.y, bb.z, bb.w};
            #pragma unroll
            for (int m = 0; m < 8; m++)
                #pragma unroll
                for (int n = 0; n < 4; n++)
                    s[m][n] = fmaf(ra[m], rb[n], s[m][n]);
        }

        // ---- mask (diagonal tile only) + stage to shared (float4) ----
        const bool diag = (kt == bx);
        #pragma unroll
        for (int m = 0; m < 8; m++) {
            const int i = ty * 8 + m;
            if (diag) {
                #pragma unroll
                for (int n = 0; n < 4; n++)
                    if (tx * 4 + n > i) s[m][n] = -1e30f;
            }
            float4 w = make_float4(s[m][0], s[m][1], s[m][2], s[m][3]);
            *reinterpret_cast<float4*>(&Ss[i * SS_STRIDE + tx * 4]) = w;
        }
        __syncthreads();

        if (have_next) sts_k();   // safe: S-GEMM done reading Ks

        // ---- online softmax: 4 threads per row ----
        {
            const int i  = tid >> 2;
            const int qq = tid & 3;
            float* row = Ss + i * SS_STRIDE + qq * 32;
            float4 xv[8];
            float mx = -1e30f;
            #pragma unroll
            for (int c = 0; c < 8; c++) {
                xv[c] = *reinterpret_cast<const float4*>(&row[c * 4]);
                mx = fmaxf(mx, fmaxf(fmaxf(xv[c].x, xv[c].y), fmaxf(xv[c].z, xv[c].w)));
            }
            mx = fmaxf(mx, __shfl_xor_sync(0xffffffffu, mx, 1));
            mx = fmaxf(mx, __shfl_xor_sync(0xffffffffu, mx, 2));
            const float mp = row_m[i];
            const float mn = fmaxf(mp, mx);
            float sum = 0.0f;
            #pragma unroll
            for (int c = 0; c < 8; c++) {
                xv[c].x = __expf(xv[c].x - mn);
                xv[c].y = __expf(xv[c].y - mn);
                xv[c].z = __expf(xv[c].z - mn);
                xv[c].w = __expf(xv[c].w - mn);
                sum += xv[c].x + xv[c].y + xv[c].z + xv[c].w;
                *reinterpret_cast<float4*>(&row[c * 4]) = xv[c];
            }
            sum += __shfl_xor_sync(0xffffffffu, sum, 1);
            sum += __shfl_xor_sync(0xffffffffu, sum, 2);
            if (qq == 0) {
                const float sc = __expf(mp - mn);
                row_s[i] = sc;
                row_m[i] = mn;
                row_l[i] = row_l[i] * sc + sum;
            }
        }
        __syncthreads();

        // ---- rescale O, accumulate P @ V (4x4 microtile, j unrolled by 4) ----
        {
            float scl[4];
            #pragma unroll
            for (int m = 0; m < 4; m++) scl[m] = row_s[ty2 * 4 + m];
            #pragma unroll
            for (int m = 0; m < 4; m++)
                #pragma unroll
                for (int n = 0; n < 4; n++) o[m][n] *= scl[m];

            #pragma unroll 8
            for (int j0 = 0; j0 < 128; j0 += 4) {
                float4 rp[4], rv[4];
                #pragma unroll
                for (int m = 0; m < 4; m++)
                    rp[m] = *reinterpret_cast<const float4*>(
                        &Ss[(ty2 * 4 + m) * SS_STRIDE + j0]);
                #pragma unroll
                for (int c = 0; c < 4; c++)
                    rv[c] = *reinterpret_cast<const float4*>(
                        &Vs[(j0 + c) * D_HEAD + tx2 * 4]);
                #pragma unroll
                for (int m = 0; m < 4; m++) {
                    o[m][0] = fmaf(rp[m].x, rv[0].x, o[m][0]);
                    o[m][1] = fmaf(rp[m].x, rv[0].y, o[m][1]);
                    o[m][2] = fmaf(rp[m].x, rv[0].z, o[m][2]);
                    o[m][3] = fmaf(rp[m].x, rv[0].w, o[m][3]);
                    o[m][0] = fmaf(rp[m].y, rv[1].x, o[m][0]);
                    o[m][1] = fmaf(rp[m].y, rv[1].y, o[m][1]);
                    o[m][2] = fmaf(rp[m].y, rv[1].z, o[m][2]);
                    o[m][3] = fmaf(rp[m].y, rv[1].w, o[m][3]);
                    o[m][0] = fmaf(rp[m].z, rv[2].x, o[m][0]);
                    o[m][1] = fmaf(rp[m].z, rv[2].y, o[m][1]);
                    o[m][2] = fmaf(rp[m].z, rv[2].z, o[m][2]);
                    o[m][3] = fmaf(rp[m].z, rv[2].w, o[m][3]);
                    o[m][0] = fmaf(rp[m].w, rv[3].x, o[m][0]);
                    o[m][1] = fmaf(rp[m].w, rv[3].y, o[m][1]);
                    o[m][2] = fmaf(rp[m].w, rv[3].z, o[m][2]);
                    o[m][3] = fmaf(rp[m].w, rv[3].w, o[m][3]);
                }
            }
        }
        __syncthreads();          // PV done reading Vs

        if (have_next) sts_v();   // next Vs; ordered before next PV by 2 syncs
    }

    // ---- normalize + write [B, T, D_MODEL] ----
    #pragma unroll
    for (int m = 0; m < 4; m++) {
        const int i = ty2 * 4 + m;
        const float inv_l = 1.0f / row_l[i];
        const int t = q0 + i;
        float4 w = make_float4(o[m][0] * inv_l, o[m][1] * inv_l,
                               o[m][2] * inv_l, o[m][3] * inv_l);
        *reinterpret_cast<float4*>(
            &out[((size_t)(b * T_SEQ + t)) * D_MODEL + h * D_HEAD + tx2 * 4]) = w;
    }
}

// ---------------------------------------------------------------------------
extern "C" void kernel_launch(void* const* d_in, const int* in_sizes, int n_in,
                              void* d_out, int out_size)
{
    const float* x  = (const float*)d_in[0];
    const float* Wq = (const float*)d_in[1];
    const float* bq = (const float*)d_in[2];
    const float* Wk = (const float*)d_in[3];
    const float* bk = (const float*)d_in[4];
    const float* Wv = (const float*)d_in[5];
    const float* bv = (const float*)d_in[6];
    const float* Wo = (const float*)d_in[7];
    const float* bo = (const float*)d_in[8];
    float* out = (float*)d_out;

    float *Q, *K, *V, *attn;
    cudaGetSymbolAddress((void**)&Q, g_Q);
    cudaGetSymbolAddress((void**)&K, g_K);
    cudaGetSymbolAddress((void**)&V, g_V);
    cudaGetSymbolAddress((void**)&attn, g_attn);

    static bool attr_set = false;
    if (!attr_set) {
        cudaFuncSetAttribute(attn_kernel,
                             cudaFuncAttributeMaxDynamicSharedMemorySize,
                             ATTN_SMEM_BYTES);
        attr_set = true;
    }

    const dim3 ggrid(D_MODEL / 128, M_ROWS / 128);  // (8, 32)
    gemm_bias_kernel<1><<<ggrid, 256>>>(x, Wq, bq, Q, M_ROWS, D_MODEL, D_MODEL);
    gemm_bias_kernel<1><<<ggrid, 256>>>(x, Wk, bk, K, M_ROWS, D_MODEL, D_MODEL);
    gemm_bias_kernel<1><<<ggrid, 256>>>(x, Wv, bv, V, M_ROWS, D_MODEL, D_MODEL);

    attn_kernel<<<dim3(T_SEQ / 128, B_SIZE * N_HEADS), 512, ATTN_SMEM_BYTES>>>(
        Q, K, V, attn);

    gemm_bias_kernel<0><<<ggrid, 256>>>(attn, Wo, bo, out, M_ROWS, D_MODEL, D_MODEL);
}

// round 3
// speedup vs baseline: 1.6510x; 1.5925x over previous
#include <cuda_runtime.h>
#include <cstdint>

#define D_MODEL 1024
#define N_HEADS 16
#define D_HEAD  64
#define B_SIZE  2
#define T_SEQ   2048
#define M_ROWS  (B_SIZE * T_SEQ)   // 4096

// Scratch (allocation-free rule: __device__ globals)
__device__ float g_Q[M_ROWS * D_MODEL];     // [B,H,T,64] head layout
__device__ float g_K[M_ROWS * D_MODEL];
__device__ float g_V[M_ROWS * D_MODEL];
__device__ float g_attn[M_ROWS * D_MODEL];  // [B,T,1024] row-major

// ===========================================================================
// TF32 tensor-core GEMM: C = A(MxK) @ W(KxN) + bias
// BM=128, BN=128, BK=32. 256 threads = 8 warps (2 M x 4 N), warp tile 64x32.
// mma.sync.m16n8k8.tf32, fp32 accum. cp.async 2-stage pipeline.
// Smem: As[2][128][36] ([m][k], stride 36 -> frag LDS conflict-free)
//       Bs[2][32][136] ([k][n], stride 136 -> frag LDS conflict-free)
// ===========================================================================
#define GEMM_SA 36
#define GEMM_SB 136
#define GEMM_AS_FLOATS (128 * GEMM_SA)          // per stage
#define GEMM_BS_FLOATS (32 * GEMM_SB)           // per stage
#define GEMM_SMEM_BYTES ((2 * GEMM_AS_FLOATS + 2 * GEMM_BS_FLOATS) * 4)

__device__ __forceinline__ uint32_t f2tf32(float x) {
    uint32_t r;
    asm("cvt.rna.tf32.f32 %0, %1;" : "=r"(r) : "f"(x));
    return r;
}

__device__ __forceinline__ void mma_tf32(float c[4], const uint32_t a[4],
                                         const uint32_t b[2]) {
    asm volatile(
        "mma.sync.aligned.m16n8k8.row.col.f32.tf32.tf32.f32 "
        "{%0,%1,%2,%3}, {%4,%5,%6,%7}, {%8,%9}, {%0,%1,%2,%3};"
        : "+f"(c[0]), "+f"(c[1]), "+f"(c[2]), "+f"(c[3])
        : "r"(a[0]), "r"(a[1]), "r"(a[2]), "r"(a[3]), "r"(b[0]), "r"(b[1]));
}

__device__ __forceinline__ void cp_async16(void* dst_smem, const void* src) {
    uint32_t d = (uint32_t)__cvta_generic_to_shared(dst_smem);
    asm volatile("cp.async.cg.shared.global [%0], [%1], 16;" ::
                 "r"(d), "l"(src));
}
__device__ __forceinline__ void cp_commit() {
    asm volatile("cp.async.commit_group;");
}
template <int N>
__device__ __forceinline__ void cp_wait() {
    asm volatile("cp.async.wait_group %0;" :: "n"(N));
}

template <int HEAD_LAYOUT>
__global__ __launch_bounds__(256)
void gemm_tf32_kernel(const float* __restrict__ A,
                      const float* __restrict__ W,
                      const float* __restrict__ bias,
                      float* __restrict__ C,
                      int M, int N, int K)
{
    extern __shared__ float sm[];
    float* As = sm;                              // [2][128][36]
    float* Bs = sm + 2 * GEMM_AS_FLOATS;         // [2][32][136]

    const int tid  = threadIdx.x;
    const int brow = blockIdx.y * 128;
    const int bcol = blockIdx.x * 128;

    const int wid  = tid >> 5;
    const int lane = tid & 31;
    const int g    = lane >> 2;          // group id 0..7
    const int t4   = lane & 3;           // thread-in-group 0..3
    const int warp_m = (wid & 1) * 64;
    const int warp_n = (wid >> 1) * 32;

    // ---- async load mappings ----
    // A: [m][k]: thread -> m = tid&127, k4 = (tid>>7) + 2*it  (it 0..3)
    const int am  = tid & 127;
    const int akq = tid >> 7;
    // B: [k][n]: thread -> n4 = tid&31, k = (tid>>5) + 8*it
    const int bn4 = tid & 31;
    const int bk  = tid >> 5;

    auto load_stage = [&](int k0, int buf) {
        float* as = As + buf * GEMM_AS_FLOATS;
        float* bs = Bs + buf * GEMM_BS_FLOATS;
        const float* ag = A + (size_t)(brow + am) * K + k0;
        #pragma unroll
        for (int it = 0; it < 4; it++) {
            const int k4 = akq + 2 * it;
            cp_async16(&as[am * GEMM_SA + k4 * 4], &ag[k4 * 4]);
        }
        #pragma unroll
        for (int it = 0; it < 4; it++) {
            const int k = bk + 8 * it;
            cp_async16(&bs[k * GEMM_SB + bn4 * 4],
                       &W[(size_t)(k0 + k) * N + bcol + bn4 * 4]);
        }
        cp_commit();
    };

    float acc[4][4][4];
    #pragma unroll
    for (int mf = 0; mf < 4; mf++)
        #pragma unroll
        for (int nf = 0; nf < 4; nf++)
            #pragma unroll
            for (int c = 0; c < 4; c++) acc[mf][nf][c] = 0.0f;

    const int nk = K / 32;
    load_stage(0, 0);

    for (int it = 0; it < nk; it++) {
        if (it + 1 < nk) {
            load_stage((it + 1) * 32, (it + 1) & 1);
            cp_wait<1>();
        } else {
            cp_wait<0>();
        }
        __syncthreads();

        const float* as = As + (it & 1) * GEMM_AS_FLOATS;
        const float* bs = Bs + (it & 1) * GEMM_BS_FLOATS;

        #pragma unroll
        for (int ks = 0; ks < 4; ks++) {
            const int kk = ks * 8;
            uint32_t af[4][4], bf[4][2];
            #pragma unroll
            for (int mf = 0; mf < 4; mf++) {
                const int m = warp_m + mf * 16 + g;
                af[mf][0] = f2tf32(as[(m    ) * GEMM_SA + kk + t4    ]);
                af[mf][1] = f2tf32(as[(m + 8) * GEMM_SA + kk + t4    ]);
                af[mf][2] = f2tf32(as[(m    ) * GEMM_SA + kk + t4 + 4]);
                af[mf][3] = f2tf32(as[(m + 8) * GEMM_SA + kk + t4 + 4]);
            }
            #pragma unroll
            for (int nf = 0; nf < 4; nf++) {
                const int n = warp_n + nf * 8 + g;
                bf[nf][0] = f2tf32(bs[(kk + t4    ) * GEMM_SB + n]);
                bf[nf][1] = f2tf32(bs[(kk + t4 + 4) * GEMM_SB + n]);
            }
            #pragma unroll
            for (int mf = 0; mf < 4; mf++)
                #pragma unroll
                for (int nf = 0; nf < 4; nf++)
                    mma_tf32(acc[mf][nf], af[mf], bf[nf]);
        }
        __syncthreads();
    }

    // ---- epilogue: bias add + store ----
    #pragma unroll
    for (int mf = 0; mf < 4; mf++) {
        #pragma unroll
        for (int nf = 0; nf < 4; nf++) {
            const int col = bcol + warp_n + nf * 8 + 2 * t4;
            const float b0 = bias[col], b1 = bias[col + 1];
            #pragma unroll
            for (int rr = 0; rr < 2; rr++) {
                const int row = brow + warp_m + mf * 16 + g + rr * 8;
                const float v0 = acc[mf][nf][rr * 2 + 0] + b0;
                const float v1 = acc[mf][nf][rr * 2 + 1] + b1;
                if (HEAD_LAYOUT) {
                    const int bb = row >> 11, tt = row & (T_SEQ - 1);
                    const int hh = col >> 6,  dd = col & 63;
                    float* p = &C[(((size_t)(bb * N_HEADS + hh) * T_SEQ) + tt)
                                  * D_HEAD + dd];
                    p[0] = v0; p[1] = v1;
                } else {
                    float* p = &C[(size_t)row * N + col];
                    p[0] = v0; p[1] = v1;
                }
            }
        }
    }
}

// ---------------------------------------------------------------------------
// Flash-attention v2 (causal), fp32 — unchanged from round 2 (passing).
// ---------------------------------------------------------------------------
#define SS_STRIDE 132
#define ATTN_SMEM_FLOATS (8192 + 8192 + 8192 + 128 * SS_STRIDE + 3 * 128)
#define ATTN_SMEM_BYTES  (ATTN_SMEM_FLOATS * 4)

__global__ __launch_bounds__(512, 1)
void attn_kernel(const float* __restrict__ Qh,
                 const float* __restrict__ Kh,
                 const float* __restrict__ Vh,
                 float* __restrict__ out)
{
    extern __shared__ float sm[];
    float* Qs    = sm;                    // [d][i]  64x128, pre-scaled
    float* Ks    = sm + 8192;             // [d][j]  64x128
    float* Vs    = sm + 16384;            // [j][d]  128x64
    float* Ss    = sm + 24576;            // [i][j]  128x132 (padded)
    float* row_m = sm + 24576 + 128 * SS_STRIDE;
    float* row_l = row_m + 128;
    float* row_s = row_l + 128;

    const int tid = threadIdx.x;
    const int bx  = gridDim.x - 1 - blockIdx.x;   // heavy blocks first
    const int bh  = blockIdx.y;
    const int b   = bh >> 4;
    const int h   = bh & 15;
    const int q0  = bx * 128;

    const float* Qb = Qh + (size_t)bh * T_SEQ * D_HEAD;
    const float* Kb = Kh + (size_t)bh * T_SEQ * D_HEAD;
    const float* Vb = Vh + (size_t)bh * T_SEQ * D_HEAD;

    {
        const int i   = tid & 127;
        const int dq0 = tid >> 7;
        #pragma unroll
        for (int it = 0; it < 4; it++) {
            const int dq = dq0 + it * 4;
            float4 v = *reinterpret_cast<const float4*>(
                &Qb[(size_t)(q0 + i) * D_HEAD + dq * 4]);
            Qs[(dq * 4 + 0) * 128 + i] = v.x * 0.125f;
            Qs[(dq * 4 + 1) * 128 + i] = v.y * 0.125f;
            Qs[(dq * 4 + 2) * 128 + i] = v.z * 0.125f;
            Qs[(dq * 4 + 3) * 128 + i] = v.w * 0.125f;
        }
    }
    if (tid < 128) { row_m[tid] = -1e30f; row_l[tid] = 0.0f; }

    const int ty  = tid >> 5;
    const int tx  = tid & 31;
    const int ty2 = tid >> 4;
    const int tx2 = tid & 15;

    float o[4][4];
    #pragma unroll
    for (int m = 0; m < 4; m++)
        #pragma unroll
        for (int n = 0; n < 4; n++) o[m][n] = 0.0f;

    const int kj  = tid & 127;
    const int kq0 = tid >> 7;
    float4 kreg[4], vreg[4];

    auto ldg_k = [&](int k0) {
        #pragma unroll
        for (int it = 0; it < 4; it++) {
            const int dq = kq0 + it * 4;
            kreg[it] = *reinterpret_cast<const float4*>(
                &Kb[(size_t)(k0 + kj) * D_HEAD + dq * 4]);
        }
    };
    auto sts_k = [&]() {
        #pragma unroll
        for (int it = 0; it < 4; it++) {
            const int dq = kq0 + it * 4;
            Ks[(dq * 4 + 0) * 128 + kj] = kreg[it].x;
            Ks[(dq * 4 + 1) * 128 + kj] = kreg[it].y;
            Ks[(dq * 4 + 2) * 128 + kj] = kreg[it].z;
            Ks[(dq * 4 + 3) * 128 + kj] = kreg[it].w;
        }
    };
    auto ldg_v = [&](int k0) {
        #pragma unroll
        for (int it = 0; it < 4; it++) {
            const int idx = tid + it * 512;
            const int j = idx >> 4, dq = idx & 15;
            vreg[it] = *reinterpret_cast<const float4*>(
                &Vb[(size_t)(k0 + j) * D_HEAD + dq * 4]);
        }
    };
    auto sts_v = [&]() {
        #pragma unroll
        for (int it = 0; it < 4; it++) {
            const int idx = tid + it * 512;
            const int j = idx >> 4, dq = idx & 15;
            *reinterpret_cast<float4*>(&Vs[j * D_HEAD + dq * 4]) = vreg[it];
        }
    };

    ldg_k(0); ldg_v(0);
    sts_k(); sts_v();
    __syncthreads();

    const int nkt = bx + 1;
    for (int kt = 0; kt < nkt; kt++) {
        const int k0 = kt * 128;
        const bool have_next = (kt + 1 < nkt);
        if (have_next) { ldg_k(k0 + 128); ldg_v(k0 + 128); }

        float s[8][4];
        #pragma unroll
        for (int m = 0; m < 8; m++)
            #pragma unroll
            for (int n = 0; n < 4; n++) s[m][n] = 0.0f;

        #pragma unroll 16
        for (int d = 0; d < D_HEAD; d++) {
            float4 a0 = *reinterpret_cast<const float4*>(&Qs[d * 128 + ty * 8]);
            float4 a1 = *reinterpret_cast<const float4*>(&Qs[d * 128 + ty * 8 + 4]);
            float4 bb = *reinterpret_cast<const float4*>(&Ks[d * 128 + tx * 4]);
            float ra[8] = {a0.x, a0.y, a0.z, a0.w, a1.x, a1.y, a1.z, a1.w};
            float rb[4] = {bb.x, bb.y, bb.z, bb.w};
            #pragma unroll
            for (int m = 0; m < 8; m++)
                #pragma unroll
                for (int n = 0; n < 4; n++)
                    s[m][n] = fmaf(ra[m], rb[n], s[m][n]);
        }

        const bool diag = (kt == bx);
        #pragma unroll
        for (int m = 0; m < 8; m++) {
            const int i = ty * 8 + m;
            if (diag) {
                #pragma unroll
                for (int n = 0; n < 4; n++)
                    if (tx * 4 + n > i) s[m][n] = -1e30f;
            }
            float4 w = make_float4(s[m][0], s[m][1], s[m][2], s[m][3]);
            *reinterpret_cast<float4*>(&Ss[i * SS_STRIDE + tx * 4]) = w;
        }
        __syncthreads();

        if (have_next) sts_k();

        {
            const int i  = tid >> 2;
            const int qq = tid & 3;
            float* row = Ss + i * SS_STRIDE + qq * 32;
            float4 xv[8];
            float mx = -1e30f;
            #pragma unroll
            for (int c = 0; c < 8; c++) {
                xv[c] = *reinterpret_cast<const float4*>(&row[c * 4]);
                mx = fmaxf(mx, fmaxf(fmaxf(xv[c].x, xv[c].y), fmaxf(xv[c].z, xv[c].w)));
            }
            mx = fmaxf(mx, __shfl_xor_sync(0xffffffffu, mx, 1));
            mx = fmaxf(mx, __shfl_xor_sync(0xffffffffu, mx, 2));
            const float mp = row_m[i];
            const float mn = fmaxf(mp, mx);
            float sum = 0.0f;
            #pragma unroll
            for (int c = 0; c < 8; c++) {
                xv[c].x = __expf(xv[c].x - mn);
                xv[c].y = __expf(xv[c].y - mn);
                xv[c].z = __expf(xv[c].z - mn);
                xv[c].w = __expf(xv[c].w - mn);
                sum += xv[c].x + xv[c].y + xv[c].z + xv[c].w;
                *reinterpret_cast<float4*>(&row[c * 4]) = xv[c];
            }
            sum += __shfl_xor_sync(0xffffffffu, sum, 1);
            sum += __shfl_xor_sync(0xffffffffu, sum, 2);
            if (qq == 0) {
                const float sc = __expf(mp - mn);
                row_s[i] = sc;
                row_m[i] = mn;
                row_l[i] = row_l[i] * sc + sum;
            }
        }
        __syncthreads();

        {
            float scl[4];
            #pragma unroll
            for (int m = 0; m < 4; m++) scl[m] = row_s[ty2 * 4 + m];
            #pragma unroll
            for (int m = 0; m < 4; m++)
                #pragma unroll
                for (int n = 0; n < 4; n++) o[m][n] *= scl[m];

            #pragma unroll 8
            for (int j0 = 0; j0 < 128; j0 += 4) {
                float4 rp[4], rv[4];
                #pragma unroll
                for (int m = 0; m < 4; m++)
                    rp[m] = *reinterpret_cast<const float4*>(
                        &Ss[(ty2 * 4 + m) * SS_STRIDE + j0]);
                #pragma unroll
                for (int c = 0; c < 4; c++)
                    rv[c] = *reinterpret_cast<const float4*>(
                        &Vs[(j0 + c) * D_HEAD + tx2 * 4]);
                #pragma unroll
                for (int m = 0; m < 4; m++) {
                    o[m][0] = fmaf(rp[m].x, rv[0].x, o[m][0]);
                    o[m][1] = fmaf(rp[m].x, rv[0].y, o[m][1]);
                    o[m][2] = fmaf(rp[m].x, rv[0].z, o[m][2]);
                    o[m][3] = fmaf(rp[m].x, rv[0].w, o[m][3]);
                    o[m][0] = fmaf(rp[m].y, rv[1].x, o[m][0]);
                    o[m][1] = fmaf(rp[m].y, rv[1].y, o[m][1]);
                    o[m][2] = fmaf(rp[m].y, rv[1].z, o[m][2]);
                    o[m][3] = fmaf(rp[m].y, rv[1].w, o[m][3]);
                    o[m][0] = fmaf(rp[m].z, rv[2].x, o[m][0]);
                    o[m][1] = fmaf(rp[m].z, rv[2].y, o[m][1]);
                    o[m][2] = fmaf(rp[m].z, rv[2].z, o[m][2]);
                    o[m][3] = fmaf(rp[m].z, rv[2].w, o[m][3]);
                    o[m][0] = fmaf(rp[m].w, rv[3].x, o[m][0]);
                    o[m][1] = fmaf(rp[m].w, rv[3].y, o[m][1]);
                    o[m][2] = fmaf(rp[m].w, rv[3].z, o[m][2]);
                    o[m][3] = fmaf(rp[m].w, rv[3].w, o[m][3]);
                }
            }
        }
        __syncthreads();

        if (have_next) sts_v();
    }

    #pragma unroll
    for (int m = 0; m < 4; m++) {
        const int i = ty2 * 4 + m;
        const float inv_l = 1.0f / row_l[i];
        const int t = q0 + i;
        float4 w = make_float4(o[m][0] * inv_l, o[m][1] * inv_l,
                               o[m][2] * inv_l, o[m][3] * inv_l);
        *reinterpret_cast<float4*>(
            &out[((size_t)(b * T_SEQ + t)) * D_MODEL + h * D_HEAD + tx2 * 4]) = w;
    }
}

// ---------------------------------------------------------------------------
extern "C" void kernel_launch(void* const* d_in, const int* in_sizes, int n_in,
                              void* d_out, int out_size)
{
    const float* x  = (const float*)d_in[0];
    const float* Wq = (const float*)d_in[1];
    const float* bq = (const float*)d_in[2];
    const float* Wk = (const float*)d_in[3];
    const float* bk = (const float*)d_in[4];
    const float* Wv = (const float*)d_in[5];
    const float* bv = (const float*)d_in[6];
    const float* Wo = (const float*)d_in[7];
    const float* bo = (const float*)d_in[8];
    float* out = (float*)d_out;

    float *Q, *K, *V, *attn;
    cudaGetSymbolAddress((void**)&Q, g_Q);
    cudaGetSymbolAddress((void**)&K, g_K);
    cudaGetSymbolAddress((void**)&V, g_V);
    cudaGetSymbolAddress((void**)&attn, g_attn);

    cudaFuncSetAttribute(gemm_tf32_kernel<1>,
                         cudaFuncAttributeMaxDynamicSharedMemorySize,
                         GEMM_SMEM_BYTES);
    cudaFuncSetAttribute(gemm_tf32_kernel<0>,
                         cudaFuncAttributeMaxDynamicSharedMemorySize,
                         GEMM_SMEM_BYTES);
    cudaFuncSetAttribute(attn_kernel,
                         cudaFuncAttributeMaxDynamicSharedMemorySize,
                         ATTN_SMEM_BYTES);

    const dim3 ggrid(D_MODEL / 128, M_ROWS / 128);  // (8, 32)
    gemm_tf32_kernel<1><<<ggrid, 256, GEMM_SMEM_BYTES>>>(
        x, Wq, bq, Q, M_ROWS, D_MODEL, D_MODEL);
    gemm_tf32_kernel<1><<<ggrid, 256, GEMM_SMEM_BYTES>>>(
        x, Wk, bk, K, M_ROWS, D_MODEL, D_MODEL);
    gemm_tf32_kernel<1><<<ggrid, 256, GEMM_SMEM_BYTES>>>(
        x, Wv, bv, V, M_ROWS, D_MODEL, D_MODEL);

    attn_kernel<<<dim3(T_SEQ / 128, B_SIZE * N_HEADS), 512, ATTN_SMEM_BYTES>>>(
        Q, K, V, attn);

    gemm_tf32_kernel<0><<<ggrid, 256, GEMM_SMEM_BYTES>>>(
        attn, Wo, bo, out, M_ROWS, D_MODEL, D_MODEL);
}

// round 4
// speedup vs baseline: 2.8010x; 1.6965x over previous
#include <cuda_runtime.h>
#include <cstdint>

#define D_MODEL 1024
#define N_HEADS 16
#define D_HEAD  64
#define B_SIZE  2
#define T_SEQ   2048
#define M_ROWS  (B_SIZE * T_SEQ)   // 4096

// Scratch (allocation-free rule: __device__ globals)
__device__ float g_Q[M_ROWS * D_MODEL];     // [B,H,T,64] head layout (pre-scaled 0.125)
__device__ float g_K[M_ROWS * D_MODEL];
__device__ float g_V[M_ROWS * D_MODEL];
__device__ float g_attn[M_ROWS * D_MODEL];  // [B,T,1024] row-major

// ===========================================================================
// Common PTX helpers
// ===========================================================================
__device__ __forceinline__ uint32_t f2tf32(float x) {
    uint32_t r;
    asm("cvt.rna.tf32.f32 %0, %1;" : "=r"(r) : "f"(x));
    return r;
}

__device__ __forceinline__ void mma_tf32(float c[4], const uint32_t a[4],
                                         const uint32_t b[2]) {
    asm volatile(
        "mma.sync.aligned.m16n8k8.row.col.f32.tf32.tf32.f32 "
        "{%0,%1,%2,%3}, {%4,%5,%6,%7}, {%8,%9}, {%0,%1,%2,%3};"
        : "+f"(c[0]), "+f"(c[1]), "+f"(c[2]), "+f"(c[3])
        : "r"(a[0]), "r"(a[1]), "r"(a[2]), "r"(a[3]), "r"(b[0]), "r"(b[1]));
}

__device__ __forceinline__ void cp_async16(void* dst_smem, const void* src) {
    uint32_t d = (uint32_t)__cvta_generic_to_shared(dst_smem);
    asm volatile("cp.async.cg.shared.global [%0], [%1], 16;" ::
                 "r"(d), "l"(src));
}
__device__ __forceinline__ void cp_commit() {
    asm volatile("cp.async.commit_group;");
}
template <int N>
__device__ __forceinline__ void cp_wait() {
    asm volatile("cp.async.wait_group %0;" :: "n"(N));
}

// ===========================================================================
// TF32 tensor-core GEMM: C = (A(MxK) @ W(KxN) + bias) * scale
// BM=128, BN=128, BK=32. 256 threads = 8 warps (2 M x 4 N), warp tile 64x32.
// ===========================================================================
#define GEMM_SA 36
#define GEMM_SB 136
#define GEMM_AS_FLOATS (128 * GEMM_SA)
#define GEMM_BS_FLOATS (32 * GEMM_SB)
#define GEMM_SMEM_BYTES ((2 * GEMM_AS_FLOATS + 2 * GEMM_BS_FLOATS) * 4)

template <int HEAD_LAYOUT>
__global__ __launch_bounds__(256)
void gemm_tf32_kernel(const float* __restrict__ A,
                      const float* __restrict__ W,
                      const float* __restrict__ bias,
                      float* __restrict__ C,
                      int M, int N, int K, float scale)
{
    extern __shared__ float sm[];
    float* As = sm;
    float* Bs = sm + 2 * GEMM_AS_FLOATS;

    const int tid  = threadIdx.x;
    const int brow = blockIdx.y * 128;
    const int bcol = blockIdx.x * 128;

    const int wid  = tid >> 5;
    const int lane = tid & 31;
    const int g    = lane >> 2;
    const int t4   = lane & 3;
    const int warp_m = (wid & 1) * 64;
    const int warp_n = (wid >> 1) * 32;

    const int am  = tid & 127;
    const int akq = tid >> 7;
    const int bn4 = tid & 31;
    const int bk  = tid >> 5;

    auto load_stage = [&](int k0, int buf) {
        float* as = As + buf * GEMM_AS_FLOATS;
        float* bs = Bs + buf * GEMM_BS_FLOATS;
        const float* ag = A + (size_t)(brow + am) * K + k0;
        #pragma unroll
        for (int it = 0; it < 4; it++) {
            const int k4 = akq + 2 * it;
            cp_async16(&as[am * GEMM_SA + k4 * 4], &ag[k4 * 4]);
        }
        #pragma unroll
        for (int it = 0; it < 4; it++) {
            const int k = bk + 8 * it;
            cp_async16(&bs[k * GEMM_SB + bn4 * 4],
                       &W[(size_t)(k0 + k) * N + bcol + bn4 * 4]);
        }
        cp_commit();
    };

    float acc[4][4][4];
    #pragma unroll
    for (int mf = 0; mf < 4; mf++)
        #pragma unroll
        for (int nf = 0; nf < 4; nf++)
            #pragma unroll
            for (int c = 0; c < 4; c++) acc[mf][nf][c] = 0.0f;

    const int nk = K / 32;
    load_stage(0, 0);

    for (int it = 0; it < nk; it++) {
        if (it + 1 < nk) {
            load_stage((it + 1) * 32, (it + 1) & 1);
            cp_wait<1>();
        } else {
            cp_wait<0>();
        }
        __syncthreads();

        const float* as = As + (it & 1) * GEMM_AS_FLOATS;
        const float* bs = Bs + (it & 1) * GEMM_BS_FLOATS;

        #pragma unroll
        for (int ks = 0; ks < 4; ks++) {
            const int kk = ks * 8;
            uint32_t af[4][4], bf[4][2];
            #pragma unroll
            for (int mf = 0; mf < 4; mf++) {
                const int m = warp_m + mf * 16 + g;
                af[mf][0] = f2tf32(as[(m    ) * GEMM_SA + kk + t4    ]);
                af[mf][1] = f2tf32(as[(m + 8) * GEMM_SA + kk + t4    ]);
                af[mf][2] = f2tf32(as[(m    ) * GEMM_SA + kk + t4 + 4]);
                af[mf][3] = f2tf32(as[(m + 8) * GEMM_SA + kk + t4 + 4]);
            }
            #pragma unroll
            for (int nf = 0; nf < 4; nf++) {
                const int n = warp_n + nf * 8 + g;
                bf[nf][0] = f2tf32(bs[(kk + t4    ) * GEMM_SB + n]);
                bf[nf][1] = f2tf32(bs[(kk + t4 + 4) * GEMM_SB + n]);
            }
            #pragma unroll
            for (int mf = 0; mf < 4; mf++)
                #pragma unroll
                for (int nf = 0; nf < 4; nf++)
                    mma_tf32(acc[mf][nf], af[mf], bf[nf]);
        }
        __syncthreads();
    }

    #pragma unroll
    for (int mf = 0; mf < 4; mf++) {
        #pragma unroll
        for (int nf = 0; nf < 4; nf++) {
            const int col = bcol + warp_n + nf * 8 + 2 * t4;
            const float b0 = bias[col], b1 = bias[col + 1];
            #pragma unroll
            for (int rr = 0; rr < 2; rr++) {
                const int row = brow + warp_m + mf * 16 + g + rr * 8;
                const float v0 = (acc[mf][nf][rr * 2 + 0] + b0) * scale;
                const float v1 = (acc[mf][nf][rr * 2 + 1] + b1) * scale;
                if (HEAD_LAYOUT) {
                    const int bb = row >> 11, tt = row & (T_SEQ - 1);
                    const int hh = col >> 6,  dd = col & 63;
                    float* p = &C[(((size_t)(bb * N_HEADS + hh) * T_SEQ) + tt)
                                  * D_HEAD + dd];
                    p[0] = v0; p[1] = v1;
                } else {
                    float* p = &C[(size_t)row * N + col];
                    p[0] = v0; p[1] = v1;
                }
            }
        }
    }
}

// ===========================================================================
// Tensor-core flash attention (causal). BQ = BKV = 128.
// 512 threads = 16 warps: wr = wid>>1 (8 row groups of 16), wc = wid&1
// (2 col halves). S warp tile 16x64, O warp tile 16x32. m16n8k8 tf32.
// Smem strides: Qs/Ks 68, Vs 72, Ss(P) 132 -> all frag LDS conflict-free.
// ===========================================================================
#define SQ 68
#define SK 68
#define SV 72
#define SP 132
#define OFF_Q  0
#define OFF_K  (128 * SQ)                 // 8704
#define OFF_V  (OFF_K + 128 * SK)         // 17408
#define OFF_S  (OFF_V + 128 * SV)         // 26624
#define OFF_RM (OFF_S + 128 * SP)         // 43520
#define OFF_RL (OFF_RM + 128)
#define OFF_RS (OFF_RL + 128)
#define OFF_PM (OFF_RS + 128)             // pmax [128][2]
#define OFF_PS (OFF_PM + 256)             // psum [128][2]
#define ATTN_SMEM_FLOATS (OFF_PS + 256)   // 44416
#define ATTN_SMEM_BYTES  (ATTN_SMEM_FLOATS * 4)

__global__ __launch_bounds__(512, 1)
void attn_mma_kernel(const float* __restrict__ Qh,
                     const float* __restrict__ Kh,
                     const float* __restrict__ Vh,
                     float* __restrict__ out)
{
    extern __shared__ float sm[];
    float* Qs    = sm + OFF_Q;
    float* Ks    = sm + OFF_K;
    float* Vs    = sm + OFF_V;
    float* Ss    = sm + OFF_S;
    float* row_m = sm + OFF_RM;
    float* row_l = sm + OFF_RL;
    float* row_s = sm + OFF_RS;
    float* pmax  = sm + OFF_PM;
    float* psum  = sm + OFF_PS;

    const int tid  = threadIdx.x;
    const int lane = tid & 31;
    const int wid  = tid >> 5;
    const int g    = lane >> 2;
    const int t4   = lane & 3;
    const int wr   = wid >> 1;           // 0..7
    const int wc   = wid & 1;            // 0..1

    const int bx = gridDim.x - 1 - blockIdx.x;   // heavy blocks first
    const int bh = blockIdx.y;
    const int b  = bh >> 4;
    const int h  = bh & 15;
    const int q0 = bx * 128;

    const float* Qb = Qh + (size_t)bh * T_SEQ * D_HEAD;
    const float* Kb = Kh + (size_t)bh * T_SEQ * D_HEAD;
    const float* Vb = Vh + (size_t)bh * T_SEQ * D_HEAD;

    // ---- async tile loaders: 128 rows x 64 floats, 16B chunks ----
    auto load_q = [&]() {
        #pragma unroll
        for (int it = 0; it < 4; it++) {
            const int id = tid + it * 512;
            const int r = id >> 4, c4 = id & 15;
            cp_async16(&Qs[r * SQ + c4 * 4], &Qb[(size_t)(q0 + r) * 64 + c4 * 4]);
        }
    };
    auto load_k = [&](int k0) {
        #pragma unroll
        for (int it = 0; it < 4; it++) {
            const int id = tid + it * 512;
            const int r = id >> 4, c4 = id & 15;
            cp_async16(&Ks[r * SK + c4 * 4], &Kb[(size_t)(k0 + r) * 64 + c4 * 4]);
        }
    };
    auto load_v = [&](int k0) {
        #pragma unroll
        for (int it = 0; it < 4; it++) {
            const int id = tid + it * 512;
            const int r = id >> 4, c4 = id & 15;
            cp_async16(&Vs[r * SV + c4 * 4], &Vb[(size_t)(k0 + r) * 64 + c4 * 4]);
        }
    };

    load_q();
    load_k(0);
    cp_commit();          // group: Q + K0
    load_v(0);
    cp_commit();          // group: V0

    if (tid < 128) { row_m[tid] = -1e30f; row_l[tid] = 0.0f; }

    float o_acc[4][4];
    #pragma unroll
    for (int nf = 0; nf < 4; nf++)
        #pragma unroll
        for (int c = 0; c < 4; c++) o_acc[nf][c] = 0.0f;

    const int r0 = wr * 16 + g;
    const int r1 = r0 + 8;
    const int nkt = bx + 1;

    for (int kt = 0; kt < nkt; kt++) {
        const bool have_next = (kt + 1 < nkt);

        cp_wait<1>();          // K(kt) (and Q) landed; V(kt) may be in flight
        __syncthreads();

        // ---- S = Q K^T : 8 k-blocks x 8 n-frags ----
        float s_acc[8][4];
        #pragma unroll
        for (int nf = 0; nf < 8; nf++)
            #pragma unroll
            for (int c = 0; c < 4; c++) s_acc[nf][c] = 0.0f;

        #pragma unroll
        for (int kb = 0; kb < 8; kb++) {
            uint32_t a[4];
            a[0] = __float_as_uint(Qs[r0 * SQ + kb * 8 + t4]);
            a[1] = __float_as_uint(Qs[r1 * SQ + kb * 8 + t4]);
            a[2] = __float_as_uint(Qs[r0 * SQ + kb * 8 + t4 + 4]);
            a[3] = __float_as_uint(Qs[r1 * SQ + kb * 8 + t4 + 4]);
            #pragma unroll
            for (int nf = 0; nf < 8; nf++) {
                const int n = wc * 64 + nf * 8 + g;
                uint32_t bfr[2];
                bfr[0] = __float_as_uint(Ks[n * SK + kb * 8 + t4]);
                bfr[1] = __float_as_uint(Ks[n * SK + kb * 8 + t4 + 4]);
                mma_tf32(s_acc[nf], a, bfr);
            }
        }

        // ---- causal mask (diagonal tile only) ----
        if (kt == bx) {
            #pragma unroll
            for (int nf = 0; nf < 8; nf++) {
                const int c0 = wc * 64 + nf * 8 + t4 * 2;
                if (c0     > r0) s_acc[nf][0] = -1e30f;
                if (c0 + 1 > r0) s_acc[nf][1] = -1e30f;
                if (c0     > r1) s_acc[nf][2] = -1e30f;
                if (c0 + 1 > r1) s_acc[nf][3] = -1e30f;
            }
        }

        // ---- partial row max over this warp's 64 cols ----
        {
            float pm0 = -1e30f, pm1 = -1e30f;
            #pragma unroll
            for (int nf = 0; nf < 8; nf++) {
                pm0 = fmaxf(pm0, fmaxf(s_acc[nf][0], s_acc[nf][1]));
                pm1 = fmaxf(pm1, fmaxf(s_acc[nf][2], s_acc[nf][3]));
            }
            pm0 = fmaxf(pm0, __shfl_xor_sync(0xffffffffu, pm0, 1));
            pm0 = fmaxf(pm0, __shfl_xor_sync(0xffffffffu, pm0, 2));
            pm1 = fmaxf(pm1, __shfl_xor_sync(0xffffffffu, pm1, 1));
            pm1 = fmaxf(pm1, __shfl_xor_sync(0xffffffffu, pm1, 2));
            if (t4 == 0) {
                pmax[r0 * 2 + wc] = pm0;
                pmax[r1 * 2 + wc] = pm1;
            }
        }
        __syncthreads();       // pmax ready; Ks free

        if (have_next) { load_k((kt + 1) * 128); cp_commit(); }

        // ---- combine row state ----
        if (tid < 128) {
            const float m_old = row_m[tid];
            const float mn = fmaxf(m_old, fmaxf(pmax[tid * 2], pmax[tid * 2 + 1]));
            row_m[tid] = mn;
            row_s[tid] = __expf(m_old - mn);
        }
        __syncthreads();       // row_m / row_s ready

        // ---- exp, P -> smem (tf32 bits), partial sums, O rescale ----
        {
            const float mn0 = row_m[r0], mn1 = row_m[r1];
            float sum0 = 0.0f, sum1 = 0.0f;
            #pragma unroll
            for (int nf = 0; nf < 8; nf++) {
                const int c0 = wc * 64 + nf * 8 + t4 * 2;
                const float p00 = __expf(s_acc[nf][0] - mn0);
                const float p01 = __expf(s_acc[nf][1] - mn0);
                const float p10 = __expf(s_acc[nf][2] - mn1);
                const float p11 = __expf(s_acc[nf][3] - mn1);
                sum0 += p00 + p01;
                sum1 += p10 + p11;
                *reinterpret_cast<uint2*>(&Ss[r0 * SP + c0]) =
                    make_uint2(f2tf32(p00), f2tf32(p01));
                *reinterpret_cast<uint2*>(&Ss[r1 * SP + c0]) =
                    make_uint2(f2tf32(p10), f2tf32(p11));
            }
            sum0 += __shfl_xor_sync(0xffffffffu, sum0, 1);
            sum0 += __shfl_xor_sync(0xffffffffu, sum0, 2);
            sum1 += __shfl_xor_sync(0xffffffffu, sum1, 1);
            sum1 += __shfl_xor_sync(0xffffffffu, sum1, 2);
            if (t4 == 0) {
                psum[r0 * 2 + wc] = sum0;
                psum[r1 * 2 + wc] = sum1;
            }
            const float sc0 = row_s[r0], sc1 = row_s[r1];
            #pragma unroll
            for (int nf = 0; nf < 4; nf++) {
                o_acc[nf][0] *= sc0; o_acc[nf][1] *= sc0;
                o_acc[nf][2] *= sc1; o_acc[nf][3] *= sc1;
            }
        }

        if (have_next) cp_wait<1>(); else cp_wait<0>();   // V(kt) landed
        __syncthreads();       // Ss + psum ready, Vs visible

        if (tid < 128)
            row_l[tid] = row_l[tid] * row_s[tid] + psum[tid * 2] + psum[tid * 2 + 1];

        // ---- O += P V : 16 k-blocks x 4 n-frags ----
        #pragma unroll
        for (int kb = 0; kb < 16; kb++) {
            uint32_t a[4];
            a[0] = __float_as_uint(Ss[r0 * SP + kb * 8 + t4]);
            a[1] = __float_as_uint(Ss[r1 * SP + kb * 8 + t4]);
            a[2] = __float_as_uint(Ss[r0 * SP + kb * 8 + t4 + 4]);
            a[3] = __float_as_uint(Ss[r1 * SP + kb * 8 + t4 + 4]);
            #pragma unroll
            for (int nf = 0; nf < 4; nf++) {
                const int n = wc * 32 + nf * 8 + g;
                uint32_t bfr[2];
                bfr[0] = f2tf32(Vs[(kb * 8 + t4) * SV + n]);
                bfr[1] = f2tf32(Vs[(kb * 8 + t4 + 4) * SV + n]);
                mma_tf32(o_acc[nf], a, bfr);
            }
        }
        __syncthreads();       // Vs free, row_s free

        if (have_next) { load_v((kt + 1) * 128); cp_commit(); }
    }

    // ---- normalize + store [B, T, D_MODEL] ----
    const float il0 = 1.0f / row_l[r0];
    const float il1 = 1.0f / row_l[r1];
    #pragma unroll
    for (int nf = 0; nf < 4; nf++) {
        const int d = wc * 32 + nf * 8 + t4 * 2;
        float* p0 = &out[((size_t)(b * T_SEQ + q0 + r0)) * D_MODEL + h * 64 + d];
        float* p1 = &out[((size_t)(b * T_SEQ + q0 + r1)) * D_MODEL + h * 64 + d];
        *reinterpret_cast<float2*>(p0) =
            make_float2(o_acc[nf][0] * il0, o_acc[nf][1] * il0);
        *reinterpret_cast<float2*>(p1) =
            make_float2(o_acc[nf][2] * il1, o_acc[nf][3] * il1);
    }
}

// ---------------------------------------------------------------------------
extern "C" void kernel_launch(void* const* d_in, const int* in_sizes, int n_in,
                              void* d_out, int out_size)
{
    const float* x  = (const float*)d_in[0];
    const float* Wq = (const float*)d_in[1];
    const float* bq = (const float*)d_in[2];
    const float* Wk = (const float*)d_in[3];
    const float* bk = (const float*)d_in[4];
    const float* Wv = (const float*)d_in[5];
    const float* bv = (const float*)d_in[6];
    const float* Wo = (const float*)d_in[7];
    const float* bo = (const float*)d_in[8];
    float* out = (float*)d_out;

    float *Q, *K, *V, *attn;
    cudaGetSymbolAddress((void**)&Q, g_Q);
    cudaGetSymbolAddress((void**)&K, g_K);
    cudaGetSymbolAddress((void**)&V, g_V);
    cudaGetSymbolAddress((void**)&attn, g_attn);

    cudaFuncSetAttribute(gemm_tf32_kernel<1>,
                         cudaFuncAttributeMaxDynamicSharedMemorySize,
                         GEMM_SMEM_BYTES);
    cudaFuncSetAttribute(gemm_tf32_kernel<0>,
                         cudaFuncAttributeMaxDynamicSharedMemorySize,
                         GEMM_SMEM_BYTES);
    cudaFuncSetAttribute(attn_mma_kernel,
                         cudaFuncAttributeMaxDynamicSharedMemorySize,
                         ATTN_SMEM_BYTES);

    const dim3 ggrid(D_MODEL / 128, M_ROWS / 128);  // (8, 32)
    gemm_tf32_kernel<1><<<ggrid, 256, GEMM_SMEM_BYTES>>>(
        x, Wq, bq, Q, M_ROWS, D_MODEL, D_MODEL, 0.125f);   // fold 1/sqrt(64)
    gemm_tf32_kernel<1><<<ggrid, 256, GEMM_SMEM_BYTES>>>(
        x, Wk, bk, K, M_ROWS, D_MODEL, D_MODEL, 1.0f);
    gemm_tf32_kernel<1><<<ggrid, 256, GEMM_SMEM_BYTES>>>(
        x, Wv, bv, V, M_ROWS, D_MODEL, D_MODEL, 1.0f);

    attn_mma_kernel<<<dim3(T_SEQ / 128, B_SIZE * N_HEADS), 512,
                      ATTN_SMEM_BYTES>>>(Q, K, V, attn);

    gemm_tf32_kernel<0><<<ggrid, 256, GEMM_SMEM_BYTES>>>(
        attn, Wo, bo, out, M_ROWS, D_MODEL, D_MODEL, 1.0f);
}

// round 5
// speedup vs baseline: 2.9234x; 1.0437x over previous
#include <cuda_runtime.h>
#include <cstdint>

#define D_MODEL 1024
#define N_HEADS 16
#define D_HEAD  64
#define B_SIZE  2
#define T_SEQ   2048
#define M_ROWS  (B_SIZE * T_SEQ)   // 4096

// Scratch (allocation-free rule: __device__ globals)
__device__ float g_Q[M_ROWS * D_MODEL];     // [B,H,T,64], pre-scaled, tf32-rounded
__device__ float g_K[M_ROWS * D_MODEL];
__device__ float g_V[M_ROWS * D_MODEL];
__device__ float g_attn[M_ROWS * D_MODEL];  // [B,T,1024], tf32-rounded
__device__ float g_xr[M_ROWS * D_MODEL];    // x rounded to tf32
__device__ float g_Wr[4][D_MODEL * D_MODEL]; // Wq,Wk,Wv,Wo rounded

// ===========================================================================
// Common PTX helpers
// ===========================================================================
__device__ __forceinline__ uint32_t f2tf32(float x) {
    uint32_t r;
    asm("cvt.rna.tf32.f32 %0, %1;" : "=r"(r) : "f"(x));
    return r;
}

__device__ __forceinline__ void mma_tf32(float c[4], const uint32_t a[4],
                                         const uint32_t b[2]) {
    asm volatile(
        "mma.sync.aligned.m16n8k8.row.col.f32.tf32.tf32.f32 "
        "{%0,%1,%2,%3}, {%4,%5,%6,%7}, {%8,%9}, {%0,%1,%2,%3};"
        : "+f"(c[0]), "+f"(c[1]), "+f"(c[2]), "+f"(c[3])
        : "r"(a[0]), "r"(a[1]), "r"(a[2]), "r"(a[3]), "r"(b[0]), "r"(b[1]));
}

__device__ __forceinline__ void cp_async16(void* dst_smem, const void* src) {
    uint32_t d = (uint32_t)__cvta_generic_to_shared(dst_smem);
    asm volatile("cp.async.cg.shared.global [%0], [%1], 16;" ::
                 "r"(d), "l"(src));
}
__device__ __forceinline__ void cp_commit() {
    asm volatile("cp.async.commit_group;");
}
template <int N>
__device__ __forceinline__ void cp_wait() {
    asm volatile("cp.async.wait_group %0;" :: "n"(N));
}

// ===========================================================================
// Elementwise tf32 rounding pre-pass (float4, grid-stride)
// ===========================================================================
__global__ void round_tf32_kernel(const float* __restrict__ src,
                                  float* __restrict__ dst, int n4)
{
    int i = blockIdx.x * blockDim.x + threadIdx.x;
    const int stride = gridDim.x * blockDim.x;
    for (; i < n4; i += stride) {
        float4 v = reinterpret_cast<const float4*>(src)[i];
        uint4 r;
        r.x = f2tf32(v.x); r.y = f2tf32(v.y);
        r.z = f2tf32(v.z); r.w = f2tf32(v.w);
        reinterpret_cast<uint4*>(dst)[i] = r;
    }
}

// ===========================================================================
// TF32 GEMM core (operands pre-rounded -> raw-bit fragments, zero cvt).
// BM=128, BN=128, BK=32. 256 threads = 8 warps (2 M x 4 N), warp tile 64x32.
// ===========================================================================
#define GEMM_SA 36
#define GEMM_SB 136
#define GEMM_AS_FLOATS (128 * GEMM_SA)
#define GEMM_BS_FLOATS (32 * GEMM_SB)
#define GEMM_SMEM_BYTES ((2 * GEMM_AS_FLOATS + 2 * GEMM_BS_FLOATS) * 4)

// Shared mainloop: accumulates A(brow:+128, :) @ W(:, bcol:+128) into acc.
__device__ __forceinline__ void gemm_mainloop(
    const float* __restrict__ A, const float* __restrict__ W,
    float* As, float* Bs, int brow, int bcol, int K, int N,
    float acc[4][4][4])
{
    const int tid  = threadIdx.x;
    const int lane = tid & 31;
    const int g    = lane >> 2;
    const int t4   = lane & 3;
    const int wid  = tid >> 5;
    const int warp_m = (wid & 1) * 64;
    const int warp_n = (wid >> 1) * 32;

    const int am  = tid & 127;
    const int akq = tid >> 7;
    const int bn4 = tid & 31;
    const int bk  = tid >> 5;

    auto load_stage = [&](int k0, int buf) {
        float* as = As + buf * GEMM_AS_FLOATS;
        float* bs = Bs + buf * GEMM_BS_FLOATS;
        const float* ag = A + (size_t)(brow + am) * K + k0;
        #pragma unroll
        for (int it = 0; it < 4; it++) {
            const int k4 = akq + 2 * it;
            cp_async16(&as[am * GEMM_SA + k4 * 4], &ag[k4 * 4]);
        }
        #pragma unroll
        for (int it = 0; it < 4; it++) {
            const int k = bk + 8 * it;
            cp_async16(&bs[k * GEMM_SB + bn4 * 4],
                       &W[(size_t)(k0 + k) * N + bcol + bn4 * 4]);
        }
        cp_commit();
    };

    const int nk = K / 32;
    load_stage(0, 0);

    for (int it = 0; it < nk; it++) {
        if (it + 1 < nk) {
            load_stage((it + 1) * 32, (it + 1) & 1);
            cp_wait<1>();
        } else {
            cp_wait<0>();
        }
        __syncthreads();

        const float* as = As + (it & 1) * GEMM_AS_FLOATS;
        const float* bs = Bs + (it & 1) * GEMM_BS_FLOATS;

        #pragma unroll
        for (int ks = 0; ks < 4; ks++) {
            const int kk = ks * 8;
            uint32_t af[4][4], bf[4][2];
            #pragma unroll
            for (int mf = 0; mf < 4; mf++) {
                const int m = warp_m + mf * 16 + g;
                af[mf][0] = __float_as_uint(as[(m    ) * GEMM_SA + kk + t4    ]);
                af[mf][1] = __float_as_uint(as[(m + 8) * GEMM_SA + kk + t4    ]);
                af[mf][2] = __float_as_uint(as[(m    ) * GEMM_SA + kk + t4 + 4]);
                af[mf][3] = __float_as_uint(as[(m + 8) * GEMM_SA + kk + t4 + 4]);
            }
            #pragma unroll
            for (int nf = 0; nf < 4; nf++) {
                const int n = warp_n + nf * 8 + g;
                bf[nf][0] = __float_as_uint(bs[(kk + t4    ) * GEMM_SB + n]);
                bf[nf][1] = __float_as_uint(bs[(kk + t4 + 4) * GEMM_SB + n]);
            }
            #pragma unroll
            for (int mf = 0; mf < 4; mf++)
                #pragma unroll
                for (int nf = 0; nf < 4; nf++)
                    mma_tf32(acc[mf][nf], af[mf], bf[nf]);
        }
        __syncthreads();
    }
}

// ---- Fused QKV projection: grid (24, 32). blockIdx.x/8 selects Q/K/V. ----
__global__ __launch_bounds__(256)
void qkv_gemm_kernel(const float* __restrict__ A,
                     const float* __restrict__ Wq, const float* __restrict__ Wk,
                     const float* __restrict__ Wv,
                     const float* __restrict__ bq, const float* __restrict__ bk,
                     const float* __restrict__ bv,
                     float* __restrict__ Qo, float* __restrict__ Ko,
                     float* __restrict__ Vo)
{
    extern __shared__ float sm[];
    float* As = sm;
    float* Bs = sm + 2 * GEMM_AS_FLOATS;

    const int wsel = blockIdx.x >> 3;           // 0=Q, 1=K, 2=V
    const int bcol = (blockIdx.x & 7) * 128;
    const int brow = blockIdx.y * 128;
    const float* W    = (wsel == 0) ? Wq : (wsel == 1) ? Wk : Wv;
    const float* bias = (wsel == 0) ? bq : (wsel == 1) ? bk : bv;
    float* C          = (wsel == 0) ? Qo : (wsel == 1) ? Ko : Vo;
    const float scale = (wsel == 0) ? 0.125f : 1.0f;

    float acc[4][4][4];
    #pragma unroll
    for (int mf = 0; mf < 4; mf++)
        #pragma unroll
        for (int nf = 0; nf < 4; nf++)
            #pragma unroll
            for (int c = 0; c < 4; c++) acc[mf][nf][c] = 0.0f;

    gemm_mainloop(A, W, As, Bs, brow, bcol, D_MODEL, D_MODEL, acc);

    const int lane = threadIdx.x & 31;
    const int g  = lane >> 2, t4 = lane & 3;
    const int wid = threadIdx.x >> 5;
    const int warp_m = (wid & 1) * 64, warp_n = (wid >> 1) * 32;

    // head-layout scatter, tf32-rounded output
    #pragma unroll
    for (int mf = 0; mf < 4; mf++) {
        #pragma unroll
        for (int nf = 0; nf < 4; nf++) {
            const int col = bcol + warp_n + nf * 8 + 2 * t4;
            const float b0 = bias[col], b1 = bias[col + 1];
            #pragma unroll
            for (int rr = 0; rr < 2; rr++) {
                const int row = brow + warp_m + mf * 16 + g + rr * 8;
                const float v0 = (acc[mf][nf][rr * 2 + 0] + b0) * scale;
                const float v1 = (acc[mf][nf][rr * 2 + 1] + b1) * scale;
                const int bb = row >> 11, tt = row & (T_SEQ - 1);
                const int hh = col >> 6,  dd = col & 63;
                float* p = &C[(((size_t)(bb * N_HEADS + hh) * T_SEQ) + tt)
                              * D_HEAD + dd];
                p[0] = __uint_as_float(f2tf32(v0));
                p[1] = __uint_as_float(f2tf32(v1));
            }
        }
    }
}

// ---- Output projection: full-fp32 epilogue ----
__global__ __launch_bounds__(256)
void out_gemm_kernel(const float* __restrict__ A, const float* __restrict__ W,
                     const float* __restrict__ bias, float* __restrict__ C)
{
    extern __shared__ float sm[];
    float* As = sm;
    float* Bs = sm + 2 * GEMM_AS_FLOATS;

    const int bcol = blockIdx.x * 128;
    const int brow = blockIdx.y * 128;

    float acc[4][4][4];
    #pragma unroll
    for (int mf = 0; mf < 4; mf++)
        #pragma unroll
        for (int nf = 0; nf < 4; nf++)
            #pragma unroll
            for (int c = 0; c < 4; c++) acc[mf][nf][c] = 0.0f;

    gemm_mainloop(A, W, As, Bs, brow, bcol, D_MODEL, D_MODEL, acc);

    const int lane = threadIdx.x & 31;
    const int g  = lane >> 2, t4 = lane & 3;
    const int wid = threadIdx.x >> 5;
    const int warp_m = (wid & 1) * 64, warp_n = (wid >> 1) * 32;

    #pragma unroll
    for (int mf = 0; mf < 4; mf++) {
        #pragma unroll
        for (int nf = 0; nf < 4; nf++) {
            const int col = bcol + warp_n + nf * 8 + 2 * t4;
            const float b0 = bias[col], b1 = bias[col + 1];
            #pragma unroll
            for (int rr = 0; rr < 2; rr++) {
                const int row = brow + warp_m + mf * 16 + g + rr * 8;
                float* p = &C[(size_t)row * D_MODEL + col];
                p[0] = acc[mf][nf][rr * 2 + 0] + b0;
                p[1] = acc[mf][nf][rr * 2 + 1] + b1;
            }
        }
    }
}

// ===========================================================================
// Tensor-core flash attention (causal). BQ = BKV = 128, 512 threads.
// Inputs pre-rounded tf32 -> all fragments raw-bit. Output tf32-rounded.
// ===========================================================================
#define SQ 68
#define SK 68
#define SV 72
#define SP 132
#define OFF_Q  0
#define OFF_K  (128 * SQ)
#define OFF_V  (OFF_K + 128 * SK)
#define OFF_S  (OFF_V + 128 * SV)
#define OFF_RM (OFF_S + 128 * SP)
#define OFF_RL (OFF_RM + 128)
#define OFF_RS (OFF_RL + 128)
#define OFF_PM (OFF_RS + 128)
#define OFF_PS (OFF_PM + 256)
#define ATTN_SMEM_FLOATS (OFF_PS + 256)
#define ATTN_SMEM_BYTES  (ATTN_SMEM_FLOATS * 4)

__global__ __launch_bounds__(512, 1)
void attn_mma_kernel(const float* __restrict__ Qh,
                     const float* __restrict__ Kh,
                     const float* __restrict__ Vh,
                     float* __restrict__ out)
{
    extern __shared__ float sm[];
    float* Qs    = sm + OFF_Q;
    float* Ks    = sm + OFF_K;
    float* Vs    = sm + OFF_V;
    float* Ss    = sm + OFF_S;
    float* row_m = sm + OFF_RM;
    float* row_l = sm + OFF_RL;
    float* row_s = sm + OFF_RS;
    float* pmax  = sm + OFF_PM;
    float* psum  = sm + OFF_PS;

    const int tid  = threadIdx.x;
    const int lane = tid & 31;
    const int wid  = tid >> 5;
    const int g    = lane >> 2;
    const int t4   = lane & 3;
    const int wr   = wid >> 1;
    const int wc   = wid & 1;

    const int bx = gridDim.x - 1 - blockIdx.x;
    const int bh = blockIdx.y;
    const int b  = bh >> 4;
    const int h  = bh & 15;
    const int q0 = bx * 128;

    const float* Qb = Qh + (size_t)bh * T_SEQ * D_HEAD;
    const float* Kb = Kh + (size_t)bh * T_SEQ * D_HEAD;
    const float* Vb = Vh + (size_t)bh * T_SEQ * D_HEAD;

    auto load_q = [&]() {
        #pragma unroll
        for (int it = 0; it < 4; it++) {
            const int id = tid + it * 512;
            const int r = id >> 4, c4 = id & 15;
            cp_async16(&Qs[r * SQ + c4 * 4], &Qb[(size_t)(q0 + r) * 64 + c4 * 4]);
        }
    };
    auto load_k = [&](int k0) {
        #pragma unroll
        for (int it = 0; it < 4; it++) {
            const int id = tid + it * 512;
            const int r = id >> 4, c4 = id & 15;
            cp_async16(&Ks[r * SK + c4 * 4], &Kb[(size_t)(k0 + r) * 64 + c4 * 4]);
        }
    };
    auto load_v = [&](int k0) {
        #pragma unroll
        for (int it = 0; it < 4; it++) {
            const int id = tid + it * 512;
            const int r = id >> 4, c4 = id & 15;
            cp_async16(&Vs[r * SV + c4 * 4], &Vb[(size_t)(k0 + r) * 64 + c4 * 4]);
        }
    };

    load_q();
    load_k(0);
    cp_commit();
    load_v(0);
    cp_commit();

    if (tid < 128) { row_m[tid] = -1e30f; row_l[tid] = 0.0f; }

    float o_acc[4][4];
    #pragma unroll
    for (int nf = 0; nf < 4; nf++)
        #pragma unroll
        for (int c = 0; c < 4; c++) o_acc[nf][c] = 0.0f;

    const int r0 = wr * 16 + g;
    const int r1 = r0 + 8;
    const int nkt = bx + 1;

    for (int kt = 0; kt < nkt; kt++) {
        const bool have_next = (kt + 1 < nkt);

        cp_wait<1>();
        __syncthreads();

        // ---- S = Q K^T ----
        float s_acc[8][4];
        #pragma unroll
        for (int nf = 0; nf < 8; nf++)
            #pragma unroll
            for (int c = 0; c < 4; c++) s_acc[nf][c] = 0.0f;

        #pragma unroll
        for (int kb = 0; kb < 8; kb++) {
            uint32_t a[4];
            a[0] = __float_as_uint(Qs[r0 * SQ + kb * 8 + t4]);
            a[1] = __float_as_uint(Qs[r1 * SQ + kb * 8 + t4]);
            a[2] = __float_as_uint(Qs[r0 * SQ + kb * 8 + t4 + 4]);
            a[3] = __float_as_uint(Qs[r1 * SQ + kb * 8 + t4 + 4]);
            #pragma unroll
            for (int nf = 0; nf < 8; nf++) {
                const int n = wc * 64 + nf * 8 + g;
                uint32_t bfr[2];
                bfr[0] = __float_as_uint(Ks[n * SK + kb * 8 + t4]);
                bfr[1] = __float_as_uint(Ks[n * SK + kb * 8 + t4 + 4]);
                mma_tf32(s_acc[nf], a, bfr);
            }
        }

        if (kt == bx) {
            #pragma unroll
            for (int nf = 0; nf < 8; nf++) {
                const int c0 = wc * 64 + nf * 8 + t4 * 2;
                if (c0     > r0) s_acc[nf][0] = -1e30f;
                if (c0 + 1 > r0) s_acc[nf][1] = -1e30f;
                if (c0     > r1) s_acc[nf][2] = -1e30f;
                if (c0 + 1 > r1) s_acc[nf][3] = -1e30f;
            }
        }

        {
            float pm0 = -1e30f, pm1 = -1e30f;
            #pragma unroll
            for (int nf = 0; nf < 8; nf++) {
                pm0 = fmaxf(pm0, fmaxf(s_acc[nf][0], s_acc[nf][1]));
                pm1 = fmaxf(pm1, fmaxf(s_acc[nf][2], s_acc[nf][3]));
            }
            pm0 = fmaxf(pm0, __shfl_xor_sync(0xffffffffu, pm0, 1));
            pm0 = fmaxf(pm0, __shfl_xor_sync(0xffffffffu, pm0, 2));
            pm1 = fmaxf(pm1, __shfl_xor_sync(0xffffffffu, pm1, 1));
            pm1 = fmaxf(pm1, __shfl_xor_sync(0xffffffffu, pm1, 2));
            if (t4 == 0) {
                pmax[r0 * 2 + wc] = pm0;
                pmax[r1 * 2 + wc] = pm1;
            }
        }
        __syncthreads();

        if (have_next) { load_k((kt + 1) * 128); cp_commit(); }

        if (tid < 128) {
            const float m_old = row_m[tid];
            const float mn = fmaxf(m_old, fmaxf(pmax[tid * 2], pmax[tid * 2 + 1]));
            row_m[tid] = mn;
            row_s[tid] = __expf(m_old - mn);
        }
        __syncthreads();

        {
            const float mn0 = row_m[r0], mn1 = row_m[r1];
            float sum0 = 0.0f, sum1 = 0.0f;
            #pragma unroll
            for (int nf = 0; nf < 8; nf++) {
                const int c0 = wc * 64 + nf * 8 + t4 * 2;
                const float p00 = __expf(s_acc[nf][0] - mn0);
                const float p01 = __expf(s_acc[nf][1] - mn0);
                const float p10 = __expf(s_acc[nf][2] - mn1);
                const float p11 = __expf(s_acc[nf][3] - mn1);
                sum0 += p00 + p01;
                sum1 += p10 + p11;
                *reinterpret_cast<uint2*>(&Ss[r0 * SP + c0]) =
                    make_uint2(f2tf32(p00), f2tf32(p01));
                *reinterpret_cast<uint2*>(&Ss[r1 * SP + c0]) =
                    make_uint2(f2tf32(p10), f2tf32(p11));
            }
            sum0 += __shfl_xor_sync(0xffffffffu, sum0, 1);
            sum0 += __shfl_xor_sync(0xffffffffu, sum0, 2);
            sum1 += __shfl_xor_sync(0xffffffffu, sum1, 1);
            sum1 += __shfl_xor_sync(0xffffffffu, sum1, 2);
            if (t4 == 0) {
                psum[r0 * 2 + wc] = sum0;
                psum[r1 * 2 + wc] = sum1;
            }
            const float sc0 = row_s[r0], sc1 = row_s[r1];
            #pragma unroll
            for (int nf = 0; nf < 4; nf++) {
                o_acc[nf][0] *= sc0; o_acc[nf][1] *= sc0;
                o_acc[nf][2] *= sc1; o_acc[nf][3] *= sc1;
            }
        }

        if (have_next) cp_wait<1>(); else cp_wait<0>();
        __syncthreads();

        if (tid < 128)
            row_l[tid] = row_l[tid] * row_s[tid] + psum[tid * 2] + psum[tid * 2 + 1];

        // ---- O += P V (V pre-rounded -> raw bits) ----
        #pragma unroll
        for (int kb = 0; kb < 16; kb++) {
            uint32_t a[4];
            a[0] = __float_as_uint(Ss[r0 * SP + kb * 8 + t4]);
            a[1] = __float_as_uint(Ss[r1 * SP + kb * 8 + t4]);
            a[2] = __float_as_uint(Ss[r0 * SP + kb * 8 + t4 + 4]);
            a[3] = __float_as_uint(Ss[r1 * SP + kb * 8 + t4 + 4]);
            #pragma unroll
            for (int nf = 0; nf < 4; nf++) {
                const int n = wc * 32 + nf * 8 + g;
                uint32_t bfr[2];
                bfr[0] = __float_as_uint(Vs[(kb * 8 + t4) * SV + n]);
                bfr[1] = __float_as_uint(Vs[(kb * 8 + t4 + 4) * SV + n]);
                mma_tf32(o_acc[nf], a, bfr);
            }
        }
        __syncthreads();

        if (have_next) { load_v((kt + 1) * 128); cp_commit(); }
    }

    // ---- normalize + store (tf32-rounded for the O-projection GEMM) ----
    const float il0 = 1.0f / row_l[r0];
    const float il1 = 1.0f / row_l[r1];
    #pragma unroll
    for (int nf = 0; nf < 4; nf++) {
        const int d = wc * 32 + nf * 8 + t4 * 2;
        float* p0 = &out[((size_t)(b * T_SEQ + q0 + r0)) * D_MODEL + h * 64 + d];
        float* p1 = &out[((size_t)(b * T_SEQ + q0 + r1)) * D_MODEL + h * 64 + d];
        *reinterpret_cast<uint2*>(p0) =
            make_uint2(f2tf32(o_acc[nf][0] * il0), f2tf32(o_acc[nf][1] * il0));
        *reinterpret_cast<uint2*>(p1) =
            make_uint2(f2tf32(o_acc[nf][2] * il1), f2tf32(o_acc[nf][3] * il1));
    }
}

// ---------------------------------------------------------------------------
extern "C" void kernel_launch(void* const* d_in, const int* in_sizes, int n_in,
                              void* d_out, int out_size)
{
    const float* x  = (const float*)d_in[0];
    const float* Wq = (const float*)d_in[1];
    const float* bq = (const float*)d_in[2];
    const float* Wk = (const float*)d_in[3];
    const float* bk = (const float*)d_in[4];
    const float* Wv = (const float*)d_in[5];
    const float* bv = (const float*)d_in[6];
    const float* Wo = (const float*)d_in[7];
    const float* bo = (const float*)d_in[8];
    float* out = (float*)d_out;

    float *Q, *K, *V, *attn, *xr, *Wr;
    cudaGetSymbolAddress((void**)&Q, g_Q);
    cudaGetSymbolAddress((void**)&K, g_K);
    cudaGetSymbolAddress((void**)&V, g_V);
    cudaGetSymbolAddress((void**)&attn, g_attn);
    cudaGetSymbolAddress((void**)&xr, g_xr);
    cudaGetSymbolAddress((void**)&Wr, g_Wr);
    float* Wqr = Wr;
    float* Wkr = Wr + (size_t)D_MODEL * D_MODEL;
    float* Wvr = Wr + (size_t)2 * D_MODEL * D_MODEL;
    float* Wor = Wr + (size_t)3 * D_MODEL * D_MODEL;

    cudaFuncSetAttribute(qkv_gemm_kernel,
                         cudaFuncAttributeMaxDynamicSharedMemorySize,
                         GEMM_SMEM_BYTES);
    cudaFuncSetAttribute(out_gemm_kernel,
                         cudaFuncAttributeMaxDynamicSharedMemorySize,
                         GEMM_SMEM_BYTES);
    cudaFuncSetAttribute(attn_mma_kernel,
                         cudaFuncAttributeMaxDynamicSharedMemorySize,
                         ATTN_SMEM_BYTES);

    // ---- pre-round operands to tf32 ----
    const int wn4 = D_MODEL * D_MODEL / 4;     // 262144
    const int xn4 = M_ROWS * D_MODEL / 4;      // 1048576
    round_tf32_kernel<<<592, 256>>>(x,  xr,  xn4);
    round_tf32_kernel<<<592, 256>>>(Wq, Wqr, wn4);
    round_tf32_kernel<<<592, 256>>>(Wk, Wkr, wn4);
    round_tf32_kernel<<<592, 256>>>(Wv, Wvr, wn4);
    round_tf32_kernel<<<592, 256>>>(Wo, Wor, wn4);

    // ---- fused QKV projection ----
    qkv_gemm_kernel<<<dim3(24, 32), 256, GEMM_SMEM_BYTES>>>(
        xr, Wqr, Wkr, Wvr, bq, bk, bv, Q, K, V);

    // ---- attention ----
    attn_mma_kernel<<<dim3(T_SEQ / 128, B_SIZE * N_HEADS), 512,
                      ATTN_SMEM_BYTES>>>(Q, K, V, attn);

    // ---- output projection ----
    out_gemm_kernel<<<dim3(8, 32), 256, GEMM_SMEM_BYTES>>>(attn, Wor, bo, out);
}